// round 4
// baseline (speedup 1.0000x reference)
#include <cuda_runtime.h>
#include <cstdint>

// Problem shape (fixed per reference)
#define B   16
#define T   32
#define C   131072            // 128*32*32
#define C4  (C/4)             // 32768 float4 per b
#define HIST_T_STRIDE4 ((size_t)B * C4)   // float4 stride between timesteps
#define CHUNK4 256            // float4 per block
#define CHUNKS_PER_B (C4 / CHUNK4)        // 128
#define INV_SCALE 0.2f

// Deterministic scratch: one partial score per (b, t, chunk).
__device__ float g_partials[B * T * CHUNKS_PER_B];   // 256 KB
__device__ float g_weights[B * T];

// Streaming load (evict-first): history has zero reuse.
__device__ __forceinline__ float4 ldcs4(const float4* p) {
    float4 v;
    asm volatile("ld.global.cs.v4.f32 {%0,%1,%2,%3}, [%4];"
                 : "=f"(v.x), "=f"(v.y), "=f"(v.z), "=f"(v.w) : "l"(p));
    return v;
}

__device__ __forceinline__ float dot4(float4 a, float4 b) {
    return a.x * b.x + a.y * b.y + a.z * b.z + a.w * b.w;
}

// ---------------------------------------------------------------------------
// Kernel 1: partial[b][t][chunk] = dot(curr[b][chunk], hist[t][b][chunk])
// 2048 blocks x 256 threads. Warp w owns timesteps {w, w+8, w+16, w+24} and
// streams the full chunk for them: 4 live accumulators per thread (vs 32
// before) -> ~40 regs -> higher occupancy & deeper load pipelining.
// q is re-read once per warp (8x L1 reuse). Hist HBM traffic exactly 1x.
// ---------------------------------------------------------------------------
__global__ void __launch_bounds__(256, 6)
scores_kernel(const float4* __restrict__ curr, const float4* __restrict__ hist) {
    const int b     = blockIdx.x >> 7;               // / CHUNKS_PER_B
    const int chunk = blockIdx.x & (CHUNKS_PER_B - 1);
    const int warp  = threadIdx.x >> 5;
    const int lane  = threadIdx.x & 31;
    const size_t base = (size_t)b * C4 + chunk * CHUNK4;

    float acc0 = 0.f, acc1 = 0.f, acc2 = 0.f, acc3 = 0.f;

    #pragma unroll
    for (int kb = 0; kb < CHUNK4; kb += 32) {
        const size_t kk = base + kb + lane;
        const float4 q = __ldg(curr + kk);
        const float4* hp = hist + kk;
        float4 h0 = ldcs4(hp + (size_t)(warp +  0) * HIST_T_STRIDE4);
        float4 h1 = ldcs4(hp + (size_t)(warp +  8) * HIST_T_STRIDE4);
        float4 h2 = ldcs4(hp + (size_t)(warp + 16) * HIST_T_STRIDE4);
        float4 h3 = ldcs4(hp + (size_t)(warp + 24) * HIST_T_STRIDE4);
        acc0 += dot4(q, h0);
        acc1 += dot4(q, h1);
        acc2 += dot4(q, h2);
        acc3 += dot4(q, h3);
    }

    // Four independent warp reductions (pipelined shuffles).
    #pragma unroll
    for (int w = 16; w >= 1; w >>= 1) {
        acc0 += __shfl_xor_sync(0xffffffffu, acc0, w);
        acc1 += __shfl_xor_sync(0xffffffffu, acc1, w);
        acc2 += __shfl_xor_sync(0xffffffffu, acc2, w);
        acc3 += __shfl_xor_sync(0xffffffffu, acc3, w);
    }

    __shared__ float s_sc[T];
    if (lane == 0) {
        s_sc[warp +  0] = acc0;
        s_sc[warp +  8] = acc1;
        s_sc[warp + 16] = acc2;
        s_sc[warp + 24] = acc3;
    }
    __syncthreads();
    if (threadIdx.x < T)
        g_partials[(b * T + threadIdx.x) * CHUNKS_PER_B + chunk] = s_sc[threadIdx.x];
}

// ---------------------------------------------------------------------------
// Kernel 2: reduce partials over chunks, softmax over T per batch element.
// 16 blocks (one per b) x 1024 threads; warp w owns timestep t=w.
// ---------------------------------------------------------------------------
__global__ void __launch_bounds__(1024, 1)
softmax_kernel() {
    const int b    = blockIdx.x;
    const int warp = threadIdx.x >> 5;   // = t
    const int lane = threadIdx.x & 31;

    const float* p = &g_partials[(b * T + warp) * CHUNKS_PER_B];
    float s = p[lane] + p[lane + 32] + p[lane + 64] + p[lane + 96];

    #pragma unroll
    for (int w = 16; w >= 1; w >>= 1)
        s += __shfl_xor_sync(0xffffffffu, s, w);

    __shared__ float sc[T];
    if (lane == 0) sc[warp] = s * INV_SCALE;
    __syncthreads();

    if (warp == 0) {
        float v = sc[lane];
        float m = v;
        #pragma unroll
        for (int w = 16; w >= 1; w >>= 1)
            m = fmaxf(m, __shfl_xor_sync(0xffffffffu, m, w));
        float e = expf(v - m);
        float z = e;
        #pragma unroll
        for (int w = 16; w >= 1; w >>= 1)
            z += __shfl_xor_sync(0xffffffffu, z, w);
        g_weights[b * T + lane] = e / z;
    }
}

// ---------------------------------------------------------------------------
// Kernel 3: out[b][k] = sum_t w[b][t] * hist[t][b][k]
// One float4 per thread, 32 independent strided float4 loads (high MLP).
// ---------------------------------------------------------------------------
__global__ void __launch_bounds__(256, 4)
out_kernel(const float4* __restrict__ hist, float4* __restrict__ out) {
    const int b = blockIdx.x >> 7;
    const int k = (blockIdx.x & (CHUNKS_PER_B - 1)) * CHUNK4 + threadIdx.x;

    __shared__ float w[T];
    if (threadIdx.x < T) w[threadIdx.x] = g_weights[b * T + threadIdx.x];
    __syncthreads();

    const float4* hp = hist + (size_t)b * C4 + k;
    float4 acc = make_float4(0.f, 0.f, 0.f, 0.f);

    #pragma unroll
    for (int t = 0; t < T; t++) {
        float4 hv = ldcs4(hp + (size_t)t * HIST_T_STRIDE4);
        float wt = w[t];
        acc.x += wt * hv.x;
        acc.y += wt * hv.y;
        acc.z += wt * hv.z;
        acc.w += wt * hv.w;
    }
    out[(size_t)b * C4 + k] = acc;
}

// ---------------------------------------------------------------------------
extern "C" void kernel_launch(void* const* d_in, const int* in_sizes, int n_in,
                              void* d_out, int out_size) {
    const float4* curr = (const float4*)d_in[0];   // h_current [16,128,32,32]
    const float4* hist = (const float4*)d_in[1];   // h_history [32,16,128,32,32]
    float4* out = (float4*)d_out;

    const int grid = B * CHUNKS_PER_B;   // 2048

    scores_kernel<<<grid, 256>>>(curr, hist);
    softmax_kernel<<<B, 1024>>>();
    out_kernel<<<grid, 256>>>(hist, out);
}

// round 7
// speedup vs baseline: 1.1026x; 1.1026x over previous
#include <cuda_runtime.h>
#include <cstdint>

// Problem shape (fixed per reference)
#define B   16
#define T   32
#define C   131072            // 128*32*32
#define C4  (C/4)             // 32768 float4 per b
#define HIST_T_STRIDE4 ((size_t)B * C4)   // float4 stride between timesteps
#define CHUNK4 256            // float4 per block
#define CHUNKS_PER_B (C4 / CHUNK4)        // 128
#define GRID (B * CHUNKS_PER_B)           // 2048
#define INV_SCALE 0.2f

// Deterministic scratch (no atomics anywhere — atomic-bearing submissions have
// failed to bench 3/3 times; atomic-free ones passed 3/3).
__device__ float g_partials[B * T * CHUNKS_PER_B];   // 256 KB
__device__ float g_weights[B * T];

// ld.global.cg: L2-cached, L1-bypassed. Used in pass 1 so the tail of history
// stays L2-resident for pass 2.
__device__ __forceinline__ float4 ldcg4(const float4* p) {
    float4 v;
    asm volatile("ld.global.cg.v4.f32 {%0,%1,%2,%3}, [%4];"
                 : "=f"(v.x), "=f"(v.y), "=f"(v.z), "=f"(v.w) : "l"(p));
    return v;
}

// st.global.cs: evict-first store — output must not displace resident history.
__device__ __forceinline__ void stcs4(float4* p, float4 v) {
    asm volatile("st.global.cs.v4.f32 [%0], {%1,%2,%3,%4};"
                 :: "l"(p), "f"(v.x), "f"(v.y), "f"(v.z), "f"(v.w) : "memory");
}

// ---------------------------------------------------------------------------
// Kernel 1: partial[b][t][chunk] = dot(curr[b][chunk], hist[t][b][chunk])
// 2048 blocks x 256 threads; 32 front-batched independent loads per thread
// (per-thread MLP beats occupancy on this pattern — R3 post-mortem).
// ld.cg keeps the most-recently-streamed history resident in L2 for pass 2.
// ---------------------------------------------------------------------------
__global__ void __launch_bounds__(256, 4)
scores_kernel(const float4* __restrict__ curr, const float4* __restrict__ hist) {
    const int b     = blockIdx.x >> 7;               // / CHUNKS_PER_B
    const int chunk = blockIdx.x & (CHUNKS_PER_B - 1);
    const int k     = chunk * CHUNK4 + threadIdx.x;  // float4 index in [0, C4)
    const int lane  = threadIdx.x & 31;
    const int warp  = threadIdx.x >> 5;

    const float4 q = curr[(size_t)b * C4 + k];
    const float4* hp = hist + (size_t)b * C4 + k;

    float acc[T];
    #pragma unroll
    for (int t = 0; t < T; t++) {
        float4 hv = ldcg4(hp + (size_t)t * HIST_T_STRIDE4);
        acc[t] = q.x * hv.x + q.y * hv.y + q.z * hv.z + q.w * hv.w;
    }

    // Multi-value butterfly: after log2(32) halving steps, lane l holds the
    // warp-wide sum for timestep l. 31 shuffles per thread total.
    #pragma unroll
    for (int w = 16; w >= 1; w >>= 1) {
        const bool upper = (lane & w) != 0;
        #pragma unroll
        for (int i = 0; i < 16; i++) {
            if (i < w) {
                float send = upper ? acc[i] : acc[i + w];
                float recv = __shfl_xor_sync(0xffffffffu, send, w);
                acc[i] = (upper ? acc[i + w] : acc[i]) + recv;
            }
        }
    }
    // acc[0] on lane l = warp sum for t = l.

    __shared__ float s_part[8][T];
    s_part[warp][lane] = acc[0];
    __syncthreads();

    if (threadIdx.x < T) {
        float s = 0.0f;
        #pragma unroll
        for (int wr = 0; wr < 8; wr++) s += s_part[wr][threadIdx.x];
        g_partials[(b * T + threadIdx.x) * CHUNKS_PER_B + chunk] = s;  // [b][t][chunk]
    }
}

// ---------------------------------------------------------------------------
// Kernel 2: reduce partials over chunks, softmax over T per batch element.
// 16 blocks (one per b) x 1024 threads; warp w owns timestep t=w. ~1.5us.
// ---------------------------------------------------------------------------
__global__ void __launch_bounds__(1024, 1)
softmax_kernel() {
    const int b    = blockIdx.x;
    const int warp = threadIdx.x >> 5;   // = t
    const int lane = threadIdx.x & 31;

    const float* p = &g_partials[(b * T + warp) * CHUNKS_PER_B];
    float s = p[lane] + p[lane + 32] + p[lane + 64] + p[lane + 96];

    #pragma unroll
    for (int w = 16; w >= 1; w >>= 1)
        s += __shfl_xor_sync(0xffffffffu, s, w);

    __shared__ float sc[T];
    if (lane == 0) sc[warp] = s * INV_SCALE;
    __syncthreads();

    if (warp == 0) {
        float v = sc[lane];
        float m = v;
        #pragma unroll
        for (int w = 16; w >= 1; w >>= 1)
            m = fmaxf(m, __shfl_xor_sync(0xffffffffu, m, w));
        float e = expf(v - m);
        float z = e;
        #pragma unroll
        for (int w = 16; w >= 1; w >>= 1)
            z += __shfl_xor_sync(0xffffffffu, z, w);
        g_weights[b * T + lane] = e / z;
    }
}

// ---------------------------------------------------------------------------
// Kernel 3: out[b][k] = sum_t w[b][t] * hist[t][b][k]
// REVERSED block mapping: the first-scheduled out blocks re-read the history
// that scores_kernel's last wave just pulled into L2 -> partial L2 carry-over.
// Output stored evict-first so it doesn't displace resident history.
// ---------------------------------------------------------------------------
__global__ void __launch_bounds__(256, 4)
out_kernel(const float4* __restrict__ hist, float4* __restrict__ out) {
    const int rb = (GRID - 1) - blockIdx.x;           // global reversal
    const int b  = rb >> 7;
    const int k  = (rb & (CHUNKS_PER_B - 1)) * CHUNK4 + threadIdx.x;

    __shared__ float w[T];
    if (threadIdx.x < T) w[threadIdx.x] = g_weights[b * T + threadIdx.x];
    __syncthreads();

    const float4* hp = hist + (size_t)b * C4 + k;
    float4 acc = make_float4(0.f, 0.f, 0.f, 0.f);

    #pragma unroll
    for (int t = 0; t < T; t++) {
        float4 hv = ldcg4(hp + (size_t)t * HIST_T_STRIDE4);
        float wt = w[t];
        acc.x += wt * hv.x;
        acc.y += wt * hv.y;
        acc.z += wt * hv.z;
        acc.w += wt * hv.w;
    }
    stcs4(out + (size_t)b * C4 + k, acc);
}

// ---------------------------------------------------------------------------
extern "C" void kernel_launch(void* const* d_in, const int* in_sizes, int n_in,
                              void* d_out, int out_size) {
    const float4* curr = (const float4*)d_in[0];   // h_current [16,128,32,32]
    const float4* hist = (const float4*)d_in[1];   // h_history [32,16,128,32,32]
    float4* out = (float4*)d_out;

    scores_kernel<<<GRID, 256>>>(curr, hist);
    softmax_kernel<<<B, 1024>>>();
    out_kernel<<<GRID, 256>>>(hist, out);
}